// round 2
// baseline (speedup 1.0000x reference)
#include <cuda_runtime.h>

#define B_  32
#define T_  1024
#define D_  512
#define U_  512
#define M_  (B_ * T_)   // 32768

// ---------------- packed f32x2 helpers (Blackwell) ----------------
__device__ __forceinline__ unsigned long long pack2(float a, float b) {
    unsigned long long r;
    asm("mov.b64 %0, {%1, %2};" : "=l"(r) : "f"(a), "f"(b));
    return r;
}
__device__ __forceinline__ void fma2(unsigned long long& d, unsigned long long a, unsigned long long b) {
    asm("fma.rn.f32x2 %0, %1, %2, %0;" : "+l"(d) : "l"(a), "l"(b));
}
__device__ __forceinline__ float2 unpack2(unsigned long long v) {
    float2 f;
    asm("mov.b64 {%0, %1}, %2;" : "=f"(f.x), "=f"(f.y) : "l"(v));
    return f;
}

// =================== Kernel 1: out = X[M,512] @ W[512,512] ===================
#define BM 128
#define BN 128
#define BK 8
#define TM 8
#define TN 8

__global__ __launch_bounds__(256, 2) void xw_gemm(const float* __restrict__ A,
                                                  const float* __restrict__ W,
                                                  float* __restrict__ C) {
    __shared__ float As[BK][BM];
    __shared__ float Bs[BK][BN];

    const int tid  = threadIdx.x;
    const long crow = (long)blockIdx.y * BM;
    const long ccol = (long)blockIdx.x * BN;

    const int arow = tid >> 1;          // 0..127
    const int acol = (tid & 1) * 4;     // 0 or 4
    const int brow = tid >> 5;          // 0..7
    const int bcol = (tid & 31) * 4;    // 0..124

    const int trow = (tid >> 4) * TM;   // 0..120
    const int tcol = (tid & 15) * TN;   // 0..120

    unsigned long long acc[TM][TN / 2];
#pragma unroll
    for (int i = 0; i < TM; i++)
#pragma unroll
        for (int j = 0; j < TN / 2; j++) acc[i][j] = 0ull;

    const float* Aptr = A + crow * D_;
    const float* Wptr = W + ccol;

    for (int k0 = 0; k0 < D_; k0 += BK) {
        float4 av = *(const float4*)(Aptr + (long)arow * D_ + k0 + acol);
        As[acol + 0][arow] = av.x;
        As[acol + 1][arow] = av.y;
        As[acol + 2][arow] = av.z;
        As[acol + 3][arow] = av.w;
        float4 bv = *(const float4*)(Wptr + (long)(k0 + brow) * U_ + bcol);
        *(float4*)&Bs[brow][bcol] = bv;
        __syncthreads();

#pragma unroll
        for (int k = 0; k < BK; k++) {
            float4 a0 = *(const float4*)&As[k][trow];
            float4 a1 = *(const float4*)&As[k][trow + 4];
            ulonglong2 b0 = *(const ulonglong2*)&Bs[k][tcol];
            ulonglong2 b1 = *(const ulonglong2*)&Bs[k][tcol + 4];
            float am[TM] = {a0.x, a0.y, a0.z, a0.w, a1.x, a1.y, a1.z, a1.w};
            unsigned long long bn[4] = {b0.x, b0.y, b1.x, b1.y};
#pragma unroll
            for (int i = 0; i < TM; i++) {
                unsigned long long aa = pack2(am[i], am[i]);
#pragma unroll
                for (int j = 0; j < 4; j++) fma2(acc[i][j], aa, bn[j]);
            }
        }
        __syncthreads();
    }

#pragma unroll
    for (int i = 0; i < TM; i++) {
        float2 p0 = unpack2(acc[i][0]);
        float2 p1 = unpack2(acc[i][1]);
        float2 p2 = unpack2(acc[i][2]);
        float2 p3 = unpack2(acc[i][3]);
        float4 o0 = make_float4(p0.x, p0.y, p1.x, p1.y);
        float4 o1 = make_float4(p2.x, p2.y, p3.x, p3.y);
        float* dst = C + (crow + trow + i) * (long)U_ + ccol + tcol;
        *(float4*)dst       = o0;
        *(float4*)(dst + 4) = o1;
    }
}

// =================== Kernel 2: persistent recurrence ===================
// out[b,t,:] += out[b,t-1,:] @ R   for t = 1..T-1, grid-synced per step.
// 128 CTAs = 8 btiles (4 rows) x 16 utiles (32 cols). 256 threads = 8 kgroups x 32 lanes.
// R column slice lives in registers (64 k-values per thread, packed f32x2).

#define RB 4
#define RU 32

__device__ unsigned g_count;
__device__ unsigned g_epoch;

__device__ __forceinline__ unsigned ld_vol(const unsigned* p) {
    unsigned v;
    asm volatile("ld.volatile.global.u32 %0, [%1];" : "=r"(v) : "l"(p));
    return v;
}
__device__ __forceinline__ void st_vol(unsigned* p, unsigned v) {
    asm volatile("st.volatile.global.u32 [%0], %1;" ::"l"(p), "r"(v) : "memory");
}

__device__ __forceinline__ void grid_barrier(unsigned nblocks) {
    __syncthreads();
    if (threadIdx.x == 0) {
        unsigned e = ld_vol(&g_epoch);
        __threadfence();
        unsigned prev = atomicAdd(&g_count, 1u);
        if (prev == nblocks - 1u) {
            atomicExch(&g_count, 0u);
            __threadfence();
            st_vol(&g_epoch, e + 1u);
        } else {
            while (ld_vol(&g_epoch) == e) { }
        }
        __threadfence();
    }
    __syncthreads();
}

__global__ __launch_bounds__(256, 1) void rnn_scan(float* __restrict__ out,
                                                   const float* __restrict__ R) {
    const int tid   = threadIdx.x;
    const int kg    = tid >> 5;   // 0..7
    const int lane  = tid & 31;   // 0..31
    const int btile = blockIdx.x >> 4;   // 0..7
    const int utile = blockIdx.x & 15;   // 0..15
    const int b0    = btile * RB;
    const int u0    = utile * RU;
    const int u     = u0 + lane;

    __shared__ alignas(16) float hs[RB][D_];      // 8 KB: h_{t-1} tile
    __shared__ float red[RB][8][RU];              // 4 KB: k-group partials

    // R slice -> registers, packed pairs along k
    unsigned long long Rreg[32];
#pragma unroll
    for (int j = 0; j < 32; j++) {
        float r0 = R[(size_t)(kg * 64 + 2 * j)     * U_ + u];
        float r1 = R[(size_t)(kg * 64 + 2 * j + 1) * U_ + u];
        Rreg[j] = pack2(r0, r1);
    }

    const unsigned nb = gridDim.x;

    for (int t = 1; t < T_; t++) {
        // prefetch xw_t for this thread's output (tid<128 own outputs)
        float xwv = 0.0f;
        size_t gidx = 0;
        if (tid < 128) {
            int b = tid >> 5;
            gidx = ((size_t)(b0 + b) * T_ + t) * U_ + u0 + lane;
            xwv = __ldcg(out + gidx);
        }
        // stage h_{t-1}: 4 rows x 512 floats = 512 float4, 2 per thread
        {
            int idx = tid;
#pragma unroll
            for (int r = 0; r < 2; r++, idx += 256) {
                int b  = idx >> 7;
                int c4 = idx & 127;
                const float4* src =
                    (const float4*)(out + ((size_t)(b0 + b) * T_ + (t - 1)) * U_);
                float4 v = __ldcg(src + c4);
                *(float4*)&hs[b][c4 * 4] = v;
            }
        }
        __syncthreads();

        unsigned long long a0 = 0, a1 = 0, a2 = 0, a3 = 0;
        const ulonglong2* h0p = (const ulonglong2*)&hs[0][kg * 64];
        const ulonglong2* h1p = (const ulonglong2*)&hs[1][kg * 64];
        const ulonglong2* h2p = (const ulonglong2*)&hs[2][kg * 64];
        const ulonglong2* h3p = (const ulonglong2*)&hs[3][kg * 64];
#pragma unroll
        for (int jj = 0; jj < 16; jj++) {
            ulonglong2 v0 = h0p[jj];
            fma2(a0, v0.x, Rreg[2 * jj]); fma2(a0, v0.y, Rreg[2 * jj + 1]);
            ulonglong2 v1 = h1p[jj];
            fma2(a1, v1.x, Rreg[2 * jj]); fma2(a1, v1.y, Rreg[2 * jj + 1]);
            ulonglong2 v2 = h2p[jj];
            fma2(a2, v2.x, Rreg[2 * jj]); fma2(a2, v2.y, Rreg[2 * jj + 1]);
            ulonglong2 v3 = h3p[jj];
            fma2(a3, v3.x, Rreg[2 * jj]); fma2(a3, v3.y, Rreg[2 * jj + 1]);
        }
        float2 s0 = unpack2(a0), s1 = unpack2(a1), s2 = unpack2(a2), s3 = unpack2(a3);
        red[0][kg][lane] = s0.x + s0.y;
        red[1][kg][lane] = s1.x + s1.y;
        red[2][kg][lane] = s2.x + s2.y;
        red[3][kg][lane] = s3.x + s3.y;
        __syncthreads();

        if (tid < 128) {
            int b = tid >> 5;
            float sum = xwv;
#pragma unroll
            for (int g = 0; g < 8; g++) sum += red[b][g][lane];
            __stcg(out + gidx, sum);
            __threadfence();
        }
        grid_barrier(nb);
    }
}

// =================== launch ===================
extern "C" void kernel_launch(void* const* d_in, const int* in_sizes, int n_in,
                              void* d_out, int out_size) {
    const float* x  = (const float*)d_in[0];  // [B,T,D]
    const float* W  = (const float*)d_in[1];  // [D,U]
    const float* R  = (const float*)d_in[2];  // [U,U]
    float* out      = (float*)d_out;          // [B,T,U]

    dim3 ggrid(U_ / BN, M_ / BM);             // (4, 256)
    xw_gemm<<<ggrid, 256>>>(x, W, out);
    rnn_scan<<<128, 256>>>(out, R);
}

// round 3
// speedup vs baseline: 2.3795x; 2.3795x over previous
#include <cuda_runtime.h>
#include <cstdint>

#define B_  32
#define T_  1024
#define D_  512
#define U_  512
#define M_  (B_ * T_)   // 32768

// ---------------- packed f32x2 helpers (Blackwell) ----------------
__device__ __forceinline__ unsigned long long pack2(float a, float b) {
    unsigned long long r;
    asm("mov.b64 %0, {%1, %2};" : "=l"(r) : "f"(a), "f"(b));
    return r;
}
__device__ __forceinline__ void fma2(unsigned long long& d, unsigned long long a, unsigned long long b) {
    asm("fma.rn.f32x2 %0, %1, %2, %0;" : "+l"(d) : "l"(a), "l"(b));
}
__device__ __forceinline__ float2 unpack2(unsigned long long v) {
    float2 f;
    asm("mov.b64 {%0, %1}, %2;" : "=f"(f.x), "=f"(f.y) : "l"(v));
    return f;
}
__device__ __forceinline__ uint32_t smem_u32(const void* p) {
    uint32_t a;
    asm("{ .reg .u64 t; cvta.to.shared.u64 t, %1; cvt.u32.u64 %0, t; }" : "=r"(a) : "l"(p));
    return a;
}

// =================== Kernel 1: out = X[M,512] @ W[512,512] ===================
#define BM 128
#define BN 128
#define BK 8
#define TM 8
#define TN 8

__global__ __launch_bounds__(256, 2) void xw_gemm(const float* __restrict__ A,
                                                  const float* __restrict__ W,
                                                  float* __restrict__ C) {
    __shared__ float As[BK][BM];
    __shared__ float Bs[BK][BN];

    const int tid  = threadIdx.x;
    const long crow = (long)blockIdx.y * BM;
    const long ccol = (long)blockIdx.x * BN;

    const int arow = tid >> 1;
    const int acol = (tid & 1) * 4;
    const int brow = tid >> 5;
    const int bcol = (tid & 31) * 4;

    const int trow = (tid >> 4) * TM;
    const int tcol = (tid & 15) * TN;

    unsigned long long acc[TM][TN / 2];
#pragma unroll
    for (int i = 0; i < TM; i++)
#pragma unroll
        for (int j = 0; j < TN / 2; j++) acc[i][j] = 0ull;

    const float* Aptr = A + crow * D_;
    const float* Wptr = W + ccol;

    for (int k0 = 0; k0 < D_; k0 += BK) {
        float4 av = *(const float4*)(Aptr + (long)arow * D_ + k0 + acol);
        As[acol + 0][arow] = av.x;
        As[acol + 1][arow] = av.y;
        As[acol + 2][arow] = av.z;
        As[acol + 3][arow] = av.w;
        float4 bv = *(const float4*)(Wptr + (long)(k0 + brow) * U_ + bcol);
        *(float4*)&Bs[brow][bcol] = bv;
        __syncthreads();

#pragma unroll
        for (int k = 0; k < BK; k++) {
            float4 a0 = *(const float4*)&As[k][trow];
            float4 a1 = *(const float4*)&As[k][trow + 4];
            ulonglong2 b0 = *(const ulonglong2*)&Bs[k][tcol];
            ulonglong2 b1 = *(const ulonglong2*)&Bs[k][tcol + 4];
            float am[TM] = {a0.x, a0.y, a0.z, a0.w, a1.x, a1.y, a1.z, a1.w};
            unsigned long long bn[4] = {b0.x, b0.y, b1.x, b1.y};
#pragma unroll
            for (int i = 0; i < TM; i++) {
                unsigned long long aa = pack2(am[i], am[i]);
#pragma unroll
                for (int j = 0; j < 4; j++) fma2(acc[i][j], aa, bn[j]);
            }
        }
        __syncthreads();
    }

#pragma unroll
    for (int i = 0; i < TM; i++) {
        float2 p0 = unpack2(acc[i][0]);
        float2 p1 = unpack2(acc[i][1]);
        float2 p2 = unpack2(acc[i][2]);
        float2 p3 = unpack2(acc[i][3]);
        float4 o0 = make_float4(p0.x, p0.y, p1.x, p1.y);
        float4 o1 = make_float4(p2.x, p2.y, p3.x, p3.y);
        float* dst = C + (crow + trow + i) * (long)U_ + ccol + tcol;
        *(float4*)dst       = o0;
        *(float4*)(dst + 4) = o1;
    }
}

// =================== Kernel 2: cluster-local recurrence ===================
// 16 clusters x 8 CTAs. Cluster g owns batches {2g, 2g+1}. CTA rank r owns
// u-stripe [64r, 64r+64). R slice (512k x 64u) register-resident:
// 256 threads = 8 kgroups(64k) x 32 lanes; lane owns 2 u cols -> 128 R floats.
// Per step: compute partials -> smem reduce -> broadcast 128 h values to all
// 8 CTAs' smem via st.shared::cluster -> mbarrier (8 cluster arrivals).

#define RB 2
#define RU 64
#define CL 8

__device__ __forceinline__ void st_remote_f32(uint32_t saddr, uint32_t rank, float v) {
    asm volatile(
        "{\n\t.reg .b32 ra;\n\t"
        "mapa.shared::cluster.u32 ra, %0, %1;\n\t"
        "st.shared::cluster.b32 [ra], %2;\n\t}"
        :: "r"(saddr), "r"(rank), "r"(__float_as_uint(v)) : "memory");
}

__device__ __forceinline__ void mbar_arrive_remote(uint32_t mbar, uint32_t rank) {
    asm volatile(
        "{\n\t.reg .b32 ra;\n\t"
        "mapa.shared::cluster.u32 ra, %0, %1;\n\t"
        "mbarrier.arrive.release.cluster.shared::cluster.b64 _, [ra];\n\t}"
        :: "r"(mbar), "r"(rank) : "memory");
}

__device__ __forceinline__ void mbar_wait_cluster(uint32_t mbar, unsigned parity) {
    uint32_t done;
    do {
        asm volatile(
            "{\n\t.reg .pred p;\n\t"
            "mbarrier.try_wait.parity.acquire.cluster.shared::cta.b64 p, [%1], %2;\n\t"
            "selp.b32 %0, 1, 0, p;\n\t}"
            : "=r"(done) : "r"(mbar), "r"(parity) : "memory");
    } while (!done);
}

__global__ __launch_bounds__(256, 1) __cluster_dims__(CL, 1, 1)
void rnn_scan(float* __restrict__ out, const float* __restrict__ R) {
    __shared__ alignas(16) float hbuf[2][RB][U_];   // 8 KB double-buffered h
    __shared__ float red[8][RB][RU];                // 4 KB k-group partials
    __shared__ alignas(8) unsigned long long mbar;

    const int tid  = threadIdx.x;
    const int kg   = tid >> 5;        // 0..7, warp = kgroup
    const int lane = tid & 31;
    uint32_t crank;
    asm("mov.u32 %0, %%cluster_ctarank;" : "=r"(crank));
    const int grp = blockIdx.x >> 3;  // 0..15
    const int b0  = grp * RB;
    const int u0  = (int)crank * RU;

    // ---- R slice into registers: Rr[c][j] packs k = kg*64 + {2j, 2j+1} for u = u0 + c*32 + lane
    unsigned long long Rr[2][32];
#pragma unroll
    for (int c = 0; c < 2; c++) {
        const int u = u0 + c * 32 + lane;
        const float* Rp = R + (size_t)(kg * 64) * U_ + u;
#pragma unroll
        for (int j = 0; j < 32; j++) {
            float r0 = Rp[(size_t)(2 * j) * U_];
            float r1 = Rp[(size_t)(2 * j + 1) * U_];
            Rr[c][j] = pack2(r0, r1);
        }
    }

    const uint32_t mbar_addr = smem_u32(&mbar);
    if (tid == 0) {
        asm volatile("mbarrier.init.shared.b64 [%0], %1;" :: "r"(mbar_addr), "r"((unsigned)CL) : "memory");
    }

    // ---- h_0 = out[b, 0, :]: each CTA loads its own full copy (2 x 512 floats)
    {
        const int r  = tid >> 7;         // 0..1
        const int c4 = tid & 127;        // 0..127
        float4 v = __ldcg((const float4*)(out + ((size_t)(b0 + r) * T_) * U_) + c4);
        *(float4*)&hbuf[0][r][c4 * 4] = v;
    }
    __syncthreads();
    asm volatile("barrier.cluster.arrive.aligned;" ::: "memory");
    asm volatile("barrier.cluster.wait.aligned;" ::: "memory");

    // ---- owner-thread state (tid < 128 owns one output: b = tid>>6, uo = tid&63)
    float xw_next = 0.0f;
    size_t gbase = 0;
    uint32_t hst_loc[2];
    const int ob  = tid >> 6;
    const int ouo = tid & 63;
    if (tid < 128) {
        gbase   = ((size_t)(b0 + ob) * T_) * U_ + u0 + ouo;
        xw_next = __ldcg(out + gbase + U_);          // xw for t = 1
        hst_loc[0] = smem_u32(&hbuf[0][ob][u0 + ouo]);
        hst_loc[1] = smem_u32(&hbuf[1][ob][u0 + ouo]);
    }

    unsigned ph = 0;
    for (int t = 1; t < T_; t++) {
        const int p  = (t - 1) & 1;
        const int np = p ^ 1;
        if (t >= 2) { mbar_wait_cluster(mbar_addr, ph); ph ^= 1; }

        // ---- compute: 2 rows x 2 ucols x 64 k, h broadcast from smem
        unsigned long long a00 = 0, a01 = 0, a10 = 0, a11 = 0;
        const ulonglong2* h0p = (const ulonglong2*)&hbuf[p][0][kg * 64];
        const ulonglong2* h1p = (const ulonglong2*)&hbuf[p][1][kg * 64];
#pragma unroll
        for (int j = 0; j < 16; j++) {
            ulonglong2 v0 = h0p[j];
            ulonglong2 v1 = h1p[j];
            fma2(a00, v0.x, Rr[0][2 * j]); fma2(a00, v0.y, Rr[0][2 * j + 1]);
            fma2(a01, v0.x, Rr[1][2 * j]); fma2(a01, v0.y, Rr[1][2 * j + 1]);
            fma2(a10, v1.x, Rr[0][2 * j]); fma2(a10, v1.y, Rr[0][2 * j + 1]);
            fma2(a11, v1.x, Rr[1][2 * j]); fma2(a11, v1.y, Rr[1][2 * j + 1]);
        }
        float2 s;
        s = unpack2(a00); red[kg][0][lane]      = s.x + s.y;
        s = unpack2(a01); red[kg][0][32 + lane] = s.x + s.y;
        s = unpack2(a10); red[kg][1][lane]      = s.x + s.y;
        s = unpack2(a11); red[kg][1][32 + lane] = s.x + s.y;
        __syncthreads();

        if (tid < 128) {
            float hv = xw_next;
#pragma unroll
            for (int g = 0; g < 8; g++) hv += red[g][ob][ouo];
            __stcg(out + gbase + (size_t)t * U_, hv);           // fire-and-forget
            if (t + 1 < T_) xw_next = __ldcg(out + gbase + (size_t)(t + 1) * U_);
            // broadcast my h value to all 8 CTAs' hbuf[np] (incl. self)
            const uint32_t dst = hst_loc[np];
#pragma unroll
            for (int r2 = 0; r2 < CL; r2++) st_remote_f32(dst, (uint32_t)r2, hv);
        }
        __syncthreads();
        if (tid < CL) mbar_arrive_remote(mbar_addr, (uint32_t)tid);
    }

    asm volatile("barrier.cluster.arrive.aligned;" ::: "memory");
    asm volatile("barrier.cluster.wait.aligned;" ::: "memory");
}

// =================== launch ===================
extern "C" void kernel_launch(void* const* d_in, const int* in_sizes, int n_in,
                              void* d_out, int out_size) {
    const float* x = (const float*)d_in[0];   // [B,T,D]
    const float* W = (const float*)d_in[1];   // [D,U]
    const float* R = (const float*)d_in[2];   // [U,U]
    float* out     = (float*)d_out;           // [B,T,U]

    dim3 ggrid(U_ / BN, M_ / BM);             // (4, 256)
    xw_gemm<<<ggrid, 256>>>(x, W, out);
    rnn_scan<<<128, 256>>>(out, R);
}